// round 2
// baseline (speedup 1.0000x reference)
#include <cuda_runtime.h>

#define BATCH 8
#define NPTS  2048
#define KNN   20
#define ROWS  (BATCH*NPTS)
#define EPSBN 1e-5f
#define SLOPE 0.2f

static __device__ float g_x0[ROWS*3];
static __device__ float g_x1[ROWS*64];
static __device__ float g_x2[ROWS*64];
static __device__ float g_x3[ROWS*128];
static __device__ float g_x4[ROWS*256];
static __device__ float g_xx[ROWS];
static __device__ float g_D[(size_t)ROWS*NPTS];
static __device__ int   g_idx[ROWS*KNN];
static __device__ float g_A [ROWS*256];
static __device__ float g_Bm[ROWS*256];
static __device__ float g_h5[(size_t)ROWS*512];
static __device__ float g_S1[512];
static __device__ float g_S2[512];

__global__ void k_trans0(const float* __restrict__ x){
    int t = blockIdx.x*256 + threadIdx.x;
    if (t >= ROWS) return;
    int b = t >> 11, n = t & 2047;
    float s = 0.f;
#pragma unroll
    for (int c=0;c<3;c++){
        float v = x[((size_t)(b*3+c))*NPTS + n];
        g_x0[t*3+c] = v; s += v*v;
    }
    g_xx[t] = s;
}

template<int C>
__global__ void k_norm(const float* __restrict__ X){
    int gw = (blockIdx.x*blockDim.x + threadIdx.x) >> 5;
    int lane = threadIdx.x & 31;
    if (gw >= ROWS) return;
    const float* row = X + (size_t)gw*C;
    float s = 0.f;
    for (int c=lane;c<C;c+=32){ float v=row[c]; s += v*v; }
#pragma unroll
    for (int o=16;o;o>>=1) s += __shfl_xor_sync(0xffffffffu, s, o);
    if (lane==0) g_xx[gw] = s;
}

// D[n][m] = xx[m] - 2 x_n . x_m   (per batch, 128x128 tile, 8x8 micro)
template<int C>
__global__ void __launch_bounds__(256) k_dist(const float* __restrict__ X){
    __shared__ __align__(16) float As[8][128];
    __shared__ __align__(16) float Bs[8][128];
    int b = blockIdx.z;
    int rowBase = blockIdx.y*128, colBase = blockIdx.x*128;
    const float* Xb = X + (size_t)b*NPTS*C;
    int tid = threadIdx.x, tr = tid>>4, tc = tid&15;
    float acc[8][8];
#pragma unroll
    for (int i=0;i<8;i++)
#pragma unroll
        for (int j=0;j<8;j++) acc[i][j]=0.f;
    for (int kk=0; kk<C; kk+=8){
        int half = tid>>7, r = tid&127;
        int base = half ? colBase : rowBase;
        float vv[8];
        if constexpr (C % 8 == 0){
            const float4* p = (const float4*)(Xb + (size_t)(base+r)*C + kk);
            float4 v0=p[0], v1=p[1];
            vv[0]=v0.x;vv[1]=v0.y;vv[2]=v0.z;vv[3]=v0.w;
            vv[4]=v1.x;vv[5]=v1.y;vv[6]=v1.z;vv[7]=v1.w;
        } else {
#pragma unroll
            for (int c=0;c<8;c++) vv[c] = (kk+c<C) ? Xb[(size_t)(base+r)*C+kk+c] : 0.f;
        }
        float (*S)[128] = half ? Bs : As;
#pragma unroll
        for (int c=0;c<8;c++) S[c][r] = vv[c];
        __syncthreads();
#pragma unroll
        for (int k2=0;k2<8;k2++){
            float4 a0 = *(const float4*)&As[k2][tr*8];
            float4 a1 = *(const float4*)&As[k2][tr*8+4];
            float4 b0 = *(const float4*)&Bs[k2][tc*8];
            float4 b1 = *(const float4*)&Bs[k2][tc*8+4];
            float a[8]={a0.x,a0.y,a0.z,a0.w,a1.x,a1.y,a1.z,a1.w};
            float bb[8]={b0.x,b0.y,b0.z,b0.w,b1.x,b1.y,b1.z,b1.w};
#pragma unroll
            for (int i=0;i<8;i++)
#pragma unroll
                for (int j=0;j<8;j++) acc[i][j] += a[i]*bb[j];
        }
        __syncthreads();
    }
    const float* xxb = g_xx + b*NPTS;
    float xv[8];
#pragma unroll
    for (int j=0;j<8;j++) xv[j] = xxb[colBase + tc*8 + j];
    float* Db = g_D + (size_t)b*NPTS*NPTS;
#pragma unroll
    for (int i=0;i<8;i++){
        int r = rowBase + tr*8 + i;
        float4 o0 = make_float4(xv[0]-2.f*acc[i][0], xv[1]-2.f*acc[i][1],
                                xv[2]-2.f*acc[i][2], xv[3]-2.f*acc[i][3]);
        float4 o1 = make_float4(xv[4]-2.f*acc[i][4], xv[5]-2.f*acc[i][5],
                                xv[6]-2.f*acc[i][6], xv[7]-2.f*acc[i][7]);
        *(float4*)&Db[(size_t)r*NPTS + colBase + tc*8]     = o0;
        *(float4*)&Db[(size_t)r*NPTS + colBase + tc*8 + 4] = o1;
    }
}

// top-20 smallest per row, 1 warp/row (sorted insertion + warp merge)
__global__ void __launch_bounds__(128) k_topk(){
    int gw = (blockIdx.x*128 + threadIdx.x) >> 5;
    int lane = threadIdx.x & 31;
    if (gw >= ROWS) return;
    const float* rowp = g_D + (size_t)gw*NPTS;
    float v[KNN]; int id[KNN];
#pragma unroll
    for (int j=0;j<KNN;j++){ v[j]=3.4e38f; id[j]=0x7fffffff; }
    for (int m=lane; m<NPTS; m+=32){
        float val = __ldg(&rowp[m]);
        if (val < v[KNN-1]){
            v[KNN-1]=val; id[KNN-1]=m;
#pragma unroll
            for (int j=KNN-1;j>0;j--){
                bool sw = (v[j] < v[j-1]) || (v[j]==v[j-1] && id[j]<id[j-1]);
                if (sw){ float tv=v[j]; v[j]=v[j-1]; v[j-1]=tv;
                         int ti=id[j]; id[j]=id[j-1]; id[j-1]=ti; }
            }
        }
    }
    int* outp = g_idx + gw*KNN;
    for (int r=0;r<KNN;r++){
        float bv = v[0]; int bi = id[0];
#pragma unroll
        for (int off=16; off; off>>=1){
            float ov = __shfl_xor_sync(0xffffffffu, bv, off);
            int   oi = __shfl_xor_sync(0xffffffffu, bi, off);
            if (ov < bv || (ov==bv && oi<bi)){ bv=ov; bi=oi; }
        }
        if (v[0]==bv && id[0]==bi){
#pragma unroll
            for (int j=0;j<KNN-1;j++){ v[j]=v[j+1]; id[j]=id[j+1]; }
            v[KNN-1]=3.4e38f; id[KNN-1]=0x7fffffff;
        }
        if (lane==0) outp[r]=bi;
    }
}

// A = Wd.x ; Bm = (Wc-Wd).x   (64x64 tile, 4x4 micro). Also zeroes stats.
template<int C,int O>
__global__ void __launch_bounds__(256) k_ab(const float* __restrict__ X, const float* __restrict__ W,
                                            float* __restrict__ Aout, float* __restrict__ Bout){
    __shared__ float Xs[8][64], Wds[8][64], Wms[8][64];
    int oBase = blockIdx.x*64, rowBase = blockIdx.y*64;
    int tid = threadIdx.x;
    if (blockIdx.x==0 && blockIdx.y==0){ g_S1[tid]=0.f; g_S2[tid]=0.f; }
    int tr = tid>>4, tc = tid&15;
    float accA[4][4], accB[4][4];
#pragma unroll
    for (int i=0;i<4;i++)
#pragma unroll
        for (int j=0;j<4;j++){ accA[i][j]=0.f; accB[i][j]=0.f; }
    for (int kk=0; kk<C; kk+=8){
        for (int t=tid; t<3*512; t+=256){
            int tile=t>>9, idx=t&511, r=idx&63, c=idx>>6;
            float val = 0.f;
            if (kk+c < C){
                if (tile==0)      val = X[(size_t)(rowBase+r)*C + kk + c];
                else if (tile==1) val = W[(size_t)(oBase+r)*(2*C) + kk + c];
                else              val = W[(size_t)(oBase+r)*(2*C) + C + kk + c]
                                      - W[(size_t)(oBase+r)*(2*C) + kk + c];
            }
            if (tile==0) Xs[c][r]=val; else if (tile==1) Wds[c][r]=val; else Wms[c][r]=val;
        }
        __syncthreads();
#pragma unroll
        for (int k2=0;k2<8;k2++){
            float a[4],d[4],m[4];
#pragma unroll
            for (int i=0;i<4;i++) a[i]=Xs[k2][tr*4+i];
#pragma unroll
            for (int j=0;j<4;j++){ d[j]=Wds[k2][tc*4+j]; m[j]=Wms[k2][tc*4+j]; }
#pragma unroll
            for (int i=0;i<4;i++)
#pragma unroll
                for (int j=0;j<4;j++){ accA[i][j]+=a[i]*d[j]; accB[i][j]+=a[i]*m[j]; }
        }
        __syncthreads();
    }
#pragma unroll
    for (int i=0;i<4;i++){
        int row = rowBase + tr*4 + i;
#pragma unroll
        for (int j=0;j<4;j++){
            int o = oBase + tc*4 + j;
            Aout[(size_t)row*O + o] = accA[i][j];
            Bout[(size_t)row*O + o] = accB[i][j];
        }
    }
}

// gather neighbors, max over k, accumulate channel moments of raw h
template<int O>
__global__ void k_gather(const float* __restrict__ A, const float* __restrict__ Bm,
                         float* __restrict__ hout){
    __shared__ int sidx[8*KNN];
    int row0 = blockIdx.x*8;
    int o = threadIdx.x;
    for (int l=o; l<8*KNN; l+=O) sidx[l] = g_idx[row0*KNN + l];
    __syncthreads();
    int b = row0 >> 11;
    const float* Ab = A + (size_t)b*NPTS*O;
    float s1=0.f, s2=0.f;
#pragma unroll
    for (int p=0;p<8;p++){
        int row = row0+p;
        float m = Bm[(size_t)row*O + o];
        float mx = -3.4e38f;
#pragma unroll
        for (int j=0;j<KNN;j++){
            float h = Ab[(size_t)sidx[p*KNN+j]*O + o] + m;
            mx = fmaxf(mx,h);
            s1 += h; s2 += h*h;
        }
        hout[(size_t)row*O + o] = mx;
    }
    atomicAdd(&g_S1[o], s1);
    atomicAdd(&g_S2[o], s2);
}

template<int O>
__global__ void k_apply(float* __restrict__ xio, const float* __restrict__ gam,
                        const float* __restrict__ bet){
    int t = blockIdx.x*256 + threadIdx.x;
    if (t >= ROWS*O) return;
    int o = t & (O-1);
    const float ci = 1.f/(float)(ROWS*KNN);
    float mean = g_S1[o]*ci;
    float var  = g_S2[o]*ci - mean*mean;
    float sc = gam[o]*rsqrtf(var + EPSBN);
    float sh = bet[o] - mean*sc;
    float h = xio[t]*sc + sh;
    xio[t] = h >= 0.f ? h : SLOPE*h;
}

// h5 = W5 . concat(x1,x2,x3,x4)   (128x128 tile, 8x8 micro). Zeroes stats.
__global__ void __launch_bounds__(256) k_gemm5(const float* __restrict__ W5){
    __shared__ __align__(16) float As[8][128];
    __shared__ __align__(16) float Ws[8][128];
    int oBase = blockIdx.x*128, rowBase = blockIdx.y*128;
    int tid = threadIdx.x;
    if (blockIdx.x==0 && blockIdx.y==0){
        g_S1[tid]=0.f; g_S1[tid+256]=0.f; g_S2[tid]=0.f; g_S2[tid+256]=0.f;
    }
    int tr = tid>>4, tc = tid&15;
    float acc[8][8];
#pragma unroll
    for (int i=0;i<8;i++)
#pragma unroll
        for (int j=0;j<8;j++) acc[i][j]=0.f;
    for (int kk=0; kk<512; kk+=8){
        const float* src; int cw, coff;
        if (kk < 64)     { src=g_x1; cw=64;  coff=kk;     }
        else if (kk<128) { src=g_x2; cw=64;  coff=kk-64;  }
        else if (kk<256) { src=g_x3; cw=128; coff=kk-128; }
        else             { src=g_x4; cw=256; coff=kk-256; }
        if (tid < 128){
            int r = tid;
            const float4* p = (const float4*)(src + (size_t)(rowBase+r)*cw + coff);
            float4 v0=p[0], v1=p[1];
            As[0][r]=v0.x;As[1][r]=v0.y;As[2][r]=v0.z;As[3][r]=v0.w;
            As[4][r]=v1.x;As[5][r]=v1.y;As[6][r]=v1.z;As[7][r]=v1.w;
        } else {
            int j = tid-128;
            const float4* p = (const float4*)(W5 + (size_t)(oBase+j)*512 + kk);
            float4 v0=p[0], v1=p[1];
            Ws[0][j]=v0.x;Ws[1][j]=v0.y;Ws[2][j]=v0.z;Ws[3][j]=v0.w;
            Ws[4][j]=v1.x;Ws[5][j]=v1.y;Ws[6][j]=v1.z;Ws[7][j]=v1.w;
        }
        __syncthreads();
#pragma unroll
        for (int k2=0;k2<8;k2++){
            float4 a0 = *(const float4*)&As[k2][tr*8];
            float4 a1 = *(const float4*)&As[k2][tr*8+4];
            float4 b0 = *(const float4*)&Ws[k2][tc*8];
            float4 b1 = *(const float4*)&Ws[k2][tc*8+4];
            float a[8]={a0.x,a0.y,a0.z,a0.w,a1.x,a1.y,a1.z,a1.w};
            float bb[8]={b0.x,b0.y,b0.z,b0.w,b1.x,b1.y,b1.z,b1.w};
#pragma unroll
            for (int i=0;i<8;i++)
#pragma unroll
                for (int j=0;j<8;j++) acc[i][j] += a[i]*bb[j];
        }
        __syncthreads();
    }
#pragma unroll
    for (int i=0;i<8;i++){
        int r = rowBase + tr*8 + i;
        float4 o0 = make_float4(acc[i][0],acc[i][1],acc[i][2],acc[i][3]);
        float4 o1 = make_float4(acc[i][4],acc[i][5],acc[i][6],acc[i][7]);
        *(float4*)&g_h5[(size_t)r*512 + oBase + tc*8]     = o0;
        *(float4*)&g_h5[(size_t)r*512 + oBase + tc*8 + 4] = o1;
    }
}

__global__ void k_stats5(){
    int o = threadIdx.x;
    int r0 = blockIdx.x*(ROWS/64);
    float s1=0.f, s2=0.f;
    for (int r=r0; r<r0+ROWS/64; r++){
        float v = g_h5[(size_t)r*512 + o];
        s1 += v; s2 += v*v;
    }
    atomicAdd(&g_S1[o], s1);
    atomicAdd(&g_S2[o], s2);
}

__global__ void k_pool(const float* __restrict__ gam, const float* __restrict__ bet,
                       float* __restrict__ out){
    int b = blockIdx.x, o = threadIdx.x;
    const float ci = 1.f/(float)ROWS;
    float mean = g_S1[o]*ci;
    float var  = g_S2[o]*ci - mean*mean;
    float sc = gam[o]*rsqrtf(var + EPSBN);
    float sh = bet[o] - mean*sc;
    float mx = -3.4e38f, sum = 0.f;
    const float* hb = g_h5 + (size_t)b*NPTS*512;
#pragma unroll 4
    for (int n=0;n<NPTS;n++){
        float h = hb[(size_t)n*512 + o]*sc + sh;
        h = h >= 0.f ? h : SLOPE*h;
        mx = fmaxf(mx,h); sum += h;
    }
    out[b*1024 + o]       = mx;
    out[b*1024 + 512 + o] = sum*(1.f/(float)NPTS);
}

extern "C" void kernel_launch(void* const* d_in, const int* in_sizes, int n_in,
                              void* d_out, int out_size){
    const float* x   = (const float*)d_in[0];
    const float* W1  = (const float*)d_in[2];
    const float* G1  = (const float*)d_in[3];
    const float* Bb1 = (const float*)d_in[4];
    const float* W2  = (const float*)d_in[5];
    const float* G2  = (const float*)d_in[6];
    const float* Bb2 = (const float*)d_in[7];
    const float* W3  = (const float*)d_in[8];
    const float* G3  = (const float*)d_in[9];
    const float* Bb3 = (const float*)d_in[10];
    const float* W4  = (const float*)d_in[11];
    const float* G4  = (const float*)d_in[12];
    const float* Bb4 = (const float*)d_in[13];
    const float* W5  = (const float*)d_in[14];
    const float* G5  = (const float*)d_in[15];
    const float* Bb5 = (const float*)d_in[16];
    float* out = (float*)d_out;

    float *px0,*px1,*px2,*px3,*px4,*pA,*pB;
    cudaGetSymbolAddress((void**)&px0, g_x0);
    cudaGetSymbolAddress((void**)&px1, g_x1);
    cudaGetSymbolAddress((void**)&px2, g_x2);
    cudaGetSymbolAddress((void**)&px3, g_x3);
    cudaGetSymbolAddress((void**)&px4, g_x4);
    cudaGetSymbolAddress((void**)&pA,  g_A);
    cudaGetSymbolAddress((void**)&pB,  g_Bm);

    dim3 gd(NPTS/128, NPTS/128, BATCH);

    k_trans0<<<ROWS/256, 256>>>(x);

    // block 1: C=3 -> O=64
    k_dist<3><<<gd, 256>>>(px0);
    k_topk<<<ROWS/4, 128>>>();
    k_ab<3,64><<<dim3(1, ROWS/64), 256>>>(px0, W1, pA, pB);
    k_gather<64><<<ROWS/8, 64>>>(pA, pB, px1);
    k_apply<64><<<(ROWS*64)/256, 256>>>(px1, G1, Bb1);

    // block 2: C=64 -> O=64
    k_norm<64><<<(ROWS*32)/256, 256>>>(px1);
    k_dist<64><<<gd, 256>>>(px1);
    k_topk<<<ROWS/4, 128>>>();
    k_ab<64,64><<<dim3(1, ROWS/64), 256>>>(px1, W2, pA, pB);
    k_gather<64><<<ROWS/8, 64>>>(pA, pB, px2);
    k_apply<64><<<(ROWS*64)/256, 256>>>(px2, G2, Bb2);

    // block 3: C=64 -> O=128
    k_norm<64><<<(ROWS*32)/256, 256>>>(px2);
    k_dist<64><<<gd, 256>>>(px2);
    k_topk<<<ROWS/4, 128>>>();
    k_ab<64,128><<<dim3(2, ROWS/64), 256>>>(px2, W3, pA, pB);
    k_gather<128><<<ROWS/8, 128>>>(pA, pB, px3);
    k_apply<128><<<(ROWS*128)/256, 256>>>(px3, G3, Bb3);

    // block 4: C=128 -> O=256
    k_norm<128><<<(ROWS*32)/256, 256>>>(px3);
    k_dist<128><<<gd, 256>>>(px3);
    k_topk<<<ROWS/4, 128>>>();
    k_ab<128,256><<<dim3(4, ROWS/64), 256>>>(px3, W4, pA, pB);
    k_gather<256><<<ROWS/8, 256>>>(pA, pB, px4);
    k_apply<256><<<(ROWS*256)/256, 256>>>(px4, G4, Bb4);

    // final
    k_gemm5<<<dim3(4, ROWS/128), 256>>>(W5);
    k_stats5<<<64, 512>>>();
    k_pool<<<BATCH, 512>>>(G5, Bb5, out);
}

// round 3
// speedup vs baseline: 1.1536x; 1.1536x over previous
#include <cuda_runtime.h>

#define BATCH 8
#define NPTS  2048
#define KNN   20
#define ROWS  (BATCH*NPTS)
#define EPSBN 1e-5f
#define SLOPE 0.2f

static __device__ float g_x0[ROWS*3];
static __device__ float g_x1[ROWS*64];
static __device__ float g_x2[ROWS*64];
static __device__ float g_x3[ROWS*128];
static __device__ float g_x4[ROWS*256];
static __device__ float g_xx[ROWS];
static __device__ float g_D[(size_t)ROWS*NPTS];
static __device__ int   g_idx[ROWS*KNN];
static __device__ float g_A [ROWS*256];
static __device__ float g_Bm[ROWS*256];
static __device__ float g_h5[(size_t)ROWS*512];
static __device__ float g_S1[512];
static __device__ float g_S2[512];

__global__ void k_trans0(const float* __restrict__ x){
    int t = blockIdx.x*256 + threadIdx.x;
    if (t >= ROWS) return;
    int b = t >> 11, n = t & 2047;
    float s = 0.f;
#pragma unroll
    for (int c=0;c<3;c++){
        float v = x[((size_t)(b*3+c))*NPTS + n];
        g_x0[t*3+c] = v; s += v*v;
    }
    g_xx[t] = s;
}

template<int C>
__global__ void k_norm(const float* __restrict__ X){
    int gw = (blockIdx.x*blockDim.x + threadIdx.x) >> 5;
    int lane = threadIdx.x & 31;
    if (gw >= ROWS) return;
    const float* row = X + (size_t)gw*C;
    float s = 0.f;
    for (int c=lane;c<C;c+=32){ float v=row[c]; s += v*v; }
#pragma unroll
    for (int o=16;o;o>>=1) s += __shfl_xor_sync(0xffffffffu, s, o);
    if (lane==0) g_xx[gw] = s;
}

// Symmetric distance GEMM: only upper-triangle 128x128 tiles; writes both
// D[r][c] = xx[c] - 2 x_r.x_c and the transposed tile (via smem staging).
template<int C>
__global__ void __launch_bounds__(256) k_dist_sym(const float* __restrict__ X){
    __shared__ __align__(16) float As[8][128];
    __shared__ __align__(16) float Bs[8][128];
    __shared__ float Ts[64][132];
    int b = blockIdx.z;
    int t = blockIdx.x;                // triangular tile decode
    int ti = 0;
    while (t >= 16 - ti){ t -= 16 - ti; ti++; }
    int tj = ti + t;
    int rowBase = ti*128, colBase = tj*128;
    const float* Xb = X + (size_t)b*NPTS*C;
    int tid = threadIdx.x, tr = tid>>4, tc = tid&15;
    int half = tid>>7, r = tid&127;
    int base = half ? colBase : rowBase;

    float acc[8][8];
#pragma unroll
    for (int i=0;i<8;i++)
#pragma unroll
        for (int j=0;j<8;j++) acc[i][j]=0.f;

    float vv[8];
    // prefetch first K-tile
    {
        if constexpr (C % 8 == 0){
            const float4* p = (const float4*)(Xb + (size_t)(base+r)*C);
            float4 v0=p[0], v1=p[1];
            vv[0]=v0.x;vv[1]=v0.y;vv[2]=v0.z;vv[3]=v0.w;
            vv[4]=v1.x;vv[5]=v1.y;vv[6]=v1.z;vv[7]=v1.w;
        } else {
#pragma unroll
            for (int c=0;c<8;c++) vv[c] = (c<C) ? Xb[(size_t)(base+r)*C+c] : 0.f;
        }
    }
    for (int kk=0; kk<C; kk+=8){
        float (*S)[128] = half ? Bs : As;
#pragma unroll
        for (int c=0;c<8;c++) S[c][r] = vv[c];
        __syncthreads();
        if (kk+8 < C){                  // prefetch next tile (overlaps FFMAs)
            if constexpr (C % 8 == 0){
                const float4* p = (const float4*)(Xb + (size_t)(base+r)*C + kk+8);
                float4 v0=p[0], v1=p[1];
                vv[0]=v0.x;vv[1]=v0.y;vv[2]=v0.z;vv[3]=v0.w;
                vv[4]=v1.x;vv[5]=v1.y;vv[6]=v1.z;vv[7]=v1.w;
            } else {
#pragma unroll
                for (int c=0;c<8;c++) vv[c] = (kk+8+c<C) ? Xb[(size_t)(base+r)*C+kk+8+c] : 0.f;
            }
        }
#pragma unroll
        for (int k2=0;k2<8;k2++){
            float4 a0 = *(const float4*)&As[k2][tr*8];
            float4 a1 = *(const float4*)&As[k2][tr*8+4];
            float4 b0 = *(const float4*)&Bs[k2][tc*8];
            float4 b1 = *(const float4*)&Bs[k2][tc*8+4];
            float a[8]={a0.x,a0.y,a0.z,a0.w,a1.x,a1.y,a1.z,a1.w};
            float bb[8]={b0.x,b0.y,b0.z,b0.w,b1.x,b1.y,b1.z,b1.w};
#pragma unroll
            for (int i=0;i<8;i++)
#pragma unroll
                for (int j=0;j<8;j++) acc[i][j] += a[i]*bb[j];
        }
        __syncthreads();
    }

    const float* xxb = g_xx + b*NPTS;
    float* Db = g_D + (size_t)b*NPTS*NPTS;
    // direct tile store
    {
        float xv[8];
#pragma unroll
        for (int j=0;j<8;j++) xv[j] = xxb[colBase + tc*8 + j];
#pragma unroll
        for (int i=0;i<8;i++){
            int rr = rowBase + tr*8 + i;
            float4 o0 = make_float4(xv[0]-2.f*acc[i][0], xv[1]-2.f*acc[i][1],
                                    xv[2]-2.f*acc[i][2], xv[3]-2.f*acc[i][3]);
            float4 o1 = make_float4(xv[4]-2.f*acc[i][4], xv[5]-2.f*acc[i][5],
                                    xv[6]-2.f*acc[i][6], xv[7]-2.f*acc[i][7]);
            *(float4*)&Db[(size_t)rr*NPTS + colBase + tc*8]     = o0;
            *(float4*)&Db[(size_t)rr*NPTS + colBase + tc*8 + 4] = o1;
        }
    }
    // transposed tile store (skip diagonal)
    if (ti != tj){
        const float* xxr = xxb + rowBase;
#pragma unroll
        for (int ch=0; ch<2; ch++){
            __syncthreads();
            if ((tc>>3) == ch){
                int tcl = tc & 7;
#pragma unroll
                for (int i=0;i<8;i++)
#pragma unroll
                    for (int j=0;j<8;j++)
                        Ts[tcl*8+j][tr*8+i] = acc[i][j];
            }
            __syncthreads();
#pragma unroll
            for (int e=0;e<32;e++){
                int idx = tid + e*256;
                int cl = idx>>7, rr = idx&127;
                int cc = colBase + ch*64 + cl;
                Db[(size_t)cc*NPTS + rowBase + rr] = xxr[rr] - 2.f*Ts[cl][rr];
            }
        }
    }
}

// top-20 smallest per row, 1 warp/row, float4 scan
__global__ void __launch_bounds__(128) k_topk(){
    int gw = (blockIdx.x*128 + threadIdx.x) >> 5;
    int lane = threadIdx.x & 31;
    if (gw >= ROWS) return;
    const float* rowp = g_D + (size_t)gw*NPTS;
    float v[KNN]; int id[KNN];
#pragma unroll
    for (int j=0;j<KNN;j++){ v[j]=3.4e38f; id[j]=0x7fffffff; }
    for (int m0=lane*4; m0<NPTS; m0+=128){
        float4 q = *(const float4*)(rowp + m0);
        float vals[4] = {q.x,q.y,q.z,q.w};
#pragma unroll
        for (int u=0;u<4;u++){
            float val = vals[u];
            if (val < v[KNN-1]){
                v[KNN-1]=val; id[KNN-1]=m0+u;
#pragma unroll
                for (int j=KNN-1;j>0;j--){
                    bool sw = (v[j] < v[j-1]) || (v[j]==v[j-1] && id[j]<id[j-1]);
                    if (sw){ float tv=v[j]; v[j]=v[j-1]; v[j-1]=tv;
                             int ti=id[j]; id[j]=id[j-1]; id[j-1]=ti; }
                }
            }
        }
    }
    int* outp = g_idx + gw*KNN;
    for (int rsel=0;rsel<KNN;rsel++){
        float bv = v[0]; int bi = id[0];
#pragma unroll
        for (int off=16; off; off>>=1){
            float ov = __shfl_xor_sync(0xffffffffu, bv, off);
            int   oi = __shfl_xor_sync(0xffffffffu, bi, off);
            if (ov < bv || (ov==bv && oi<bi)){ bv=ov; bi=oi; }
        }
        if (v[0]==bv && id[0]==bi){
#pragma unroll
            for (int j=0;j<KNN-1;j++){ v[j]=v[j+1]; id[j]=id[j+1]; }
            v[KNN-1]=3.4e38f; id[KNN-1]=0x7fffffff;
        }
        if (lane==0) outp[rsel]=bi;
    }
}

// A = Wd.x ; Bm = (Wc-Wd).x   (64x64 tile). Also zeroes stats.
template<int C,int O>
__global__ void __launch_bounds__(256) k_ab(const float* __restrict__ X, const float* __restrict__ W,
                                            float* __restrict__ Aout, float* __restrict__ Bout){
    __shared__ float Xs[8][64], Wds[8][64], Wms[8][64];
    int oBase = blockIdx.x*64, rowBase = blockIdx.y*64;
    int tid = threadIdx.x;
    if (blockIdx.x==0 && blockIdx.y==0){ g_S1[tid]=0.f; g_S2[tid]=0.f; }
    int tr = tid>>4, tc = tid&15;
    float accA[4][4], accB[4][4];
#pragma unroll
    for (int i=0;i<4;i++)
#pragma unroll
        for (int j=0;j<4;j++){ accA[i][j]=0.f; accB[i][j]=0.f; }
    for (int kk=0; kk<C; kk+=8){
        for (int t=tid; t<3*512; t+=256){
            int tile=t>>9, idx=t&511, r=idx&63, c=idx>>6;
            float val = 0.f;
            if (kk+c < C){
                if (tile==0)      val = X[(size_t)(rowBase+r)*C + kk + c];
                else if (tile==1) val = W[(size_t)(oBase+r)*(2*C) + kk + c];
                else              val = W[(size_t)(oBase+r)*(2*C) + C + kk + c]
                                      - W[(size_t)(oBase+r)*(2*C) + kk + c];
            }
            if (tile==0) Xs[c][r]=val; else if (tile==1) Wds[c][r]=val; else Wms[c][r]=val;
        }
        __syncthreads();
#pragma unroll
        for (int k2=0;k2<8;k2++){
            float a[4],d[4],m[4];
#pragma unroll
            for (int i=0;i<4;i++) a[i]=Xs[k2][tr*4+i];
#pragma unroll
            for (int j=0;j<4;j++){ d[j]=Wds[k2][tc*4+j]; m[j]=Wms[k2][tc*4+j]; }
#pragma unroll
            for (int i=0;i<4;i++)
#pragma unroll
                for (int j=0;j<4;j++){ accA[i][j]+=a[i]*d[j]; accB[i][j]+=a[i]*m[j]; }
        }
        __syncthreads();
    }
#pragma unroll
    for (int i=0;i<4;i++){
        int row = rowBase + tr*4 + i;
#pragma unroll
        for (int j=0;j<4;j++){
            int o = oBase + tc*4 + j;
            Aout[(size_t)row*O + o] = accA[i][j];
            Bout[(size_t)row*O + o] = accB[i][j];
        }
    }
}

template<int O>
__global__ void k_gather(const float* __restrict__ A, const float* __restrict__ Bm,
                         float* __restrict__ hout){
    __shared__ int sidx[8*KNN];
    int row0 = blockIdx.x*8;
    int o = threadIdx.x;
    for (int l=o; l<8*KNN; l+=O) sidx[l] = g_idx[row0*KNN + l];
    __syncthreads();
    int b = row0 >> 11;
    const float* Ab = A + (size_t)b*NPTS*O;
    float s1=0.f, s2=0.f;
#pragma unroll
    for (int p=0;p<8;p++){
        int row = row0+p;
        float m = Bm[(size_t)row*O + o];
        float mx = -3.4e38f;
#pragma unroll
        for (int j=0;j<KNN;j++){
            float h = Ab[(size_t)sidx[p*KNN+j]*O + o] + m;
            mx = fmaxf(mx,h);
            s1 += h; s2 += h*h;
        }
        hout[(size_t)row*O + o] = mx;
    }
    atomicAdd(&g_S1[o], s1);
    atomicAdd(&g_S2[o], s2);
}

template<int O>
__global__ void k_apply(float* __restrict__ xio, const float* __restrict__ gam,
                        const float* __restrict__ bet){
    int t = blockIdx.x*256 + threadIdx.x;
    if (t >= ROWS*O) return;
    int o = t & (O-1);
    const float ci = 1.f/(float)(ROWS*KNN);
    float mean = g_S1[o]*ci;
    float var  = g_S2[o]*ci - mean*mean;
    float sc = gam[o]*rsqrtf(var + EPSBN);
    float sh = bet[o] - mean*sc;
    float h = xio[t]*sc + sh;
    xio[t] = h >= 0.f ? h : SLOPE*h;
}

// h5 = W5 . concat(x1..x4)  (128x128 tile, prefetch-double-buffered). Zeroes stats.
__global__ void __launch_bounds__(256) k_gemm5(const float* __restrict__ W5){
    __shared__ __align__(16) float As[8][128];
    __shared__ __align__(16) float Ws[8][128];
    int oBase = blockIdx.x*128, rowBase = blockIdx.y*128;
    int tid = threadIdx.x;
    if (blockIdx.x==0 && blockIdx.y==0){
        g_S1[tid]=0.f; g_S1[tid+256]=0.f; g_S2[tid]=0.f; g_S2[tid+256]=0.f;
    }
    int tr = tid>>4, tc = tid&15;
    float acc[8][8];
#pragma unroll
    for (int i=0;i<8;i++)
#pragma unroll
        for (int j=0;j<8;j++) acc[i][j]=0.f;

    float4 pf0, pf1;
    auto ld5 = [&](int kk){
        if (tid < 128){
            const float* src; int cw, coff;
            if (kk < 64)     { src=g_x1; cw=64;  coff=kk;     }
            else if (kk<128) { src=g_x2; cw=64;  coff=kk-64;  }
            else if (kk<256) { src=g_x3; cw=128; coff=kk-128; }
            else             { src=g_x4; cw=256; coff=kk-256; }
            const float4* p = (const float4*)(src + (size_t)(rowBase+tid)*cw + coff);
            pf0=p[0]; pf1=p[1];
        } else {
            const float4* p = (const float4*)(W5 + (size_t)(oBase+tid-128)*512 + kk);
            pf0=p[0]; pf1=p[1];
        }
    };
    ld5(0);
    for (int kk=0; kk<512; kk+=8){
        if (tid < 128){
            int r = tid;
            As[0][r]=pf0.x;As[1][r]=pf0.y;As[2][r]=pf0.z;As[3][r]=pf0.w;
            As[4][r]=pf1.x;As[5][r]=pf1.y;As[6][r]=pf1.z;As[7][r]=pf1.w;
        } else {
            int j = tid-128;
            Ws[0][j]=pf0.x;Ws[1][j]=pf0.y;Ws[2][j]=pf0.z;Ws[3][j]=pf0.w;
            Ws[4][j]=pf1.x;Ws[5][j]=pf1.y;Ws[6][j]=pf1.z;Ws[7][j]=pf1.w;
        }
        __syncthreads();
        if (kk+8 < 512) ld5(kk+8);
#pragma unroll
        for (int k2=0;k2<8;k2++){
            float4 a0 = *(const float4*)&As[k2][tr*8];
            float4 a1 = *(const float4*)&As[k2][tr*8+4];
            float4 b0 = *(const float4*)&Ws[k2][tc*8];
            float4 b1 = *(const float4*)&Ws[k2][tc*8+4];
            float a[8]={a0.x,a0.y,a0.z,a0.w,a1.x,a1.y,a1.z,a1.w};
            float bb[8]={b0.x,b0.y,b0.z,b0.w,b1.x,b1.y,b1.z,b1.w};
#pragma unroll
            for (int i=0;i<8;i++)
#pragma unroll
                for (int j=0;j<8;j++) acc[i][j] += a[i]*bb[j];
        }
        __syncthreads();
    }
#pragma unroll
    for (int i=0;i<8;i++){
        int r = rowBase + tr*8 + i;
        float4 o0 = make_float4(acc[i][0],acc[i][1],acc[i][2],acc[i][3]);
        float4 o1 = make_float4(acc[i][4],acc[i][5],acc[i][6],acc[i][7]);
        *(float4*)&g_h5[(size_t)r*512 + oBase + tc*8]     = o0;
        *(float4*)&g_h5[(size_t)r*512 + oBase + tc*8 + 4] = o1;
    }
}

__global__ void k_stats5(){
    int o = threadIdx.x;
    int r0 = blockIdx.x*(ROWS/64);
    float s1=0.f, s2=0.f;
    for (int r=r0; r<r0+ROWS/64; r++){
        float v = g_h5[(size_t)r*512 + o];
        s1 += v; s2 += v*v;
    }
    atomicAdd(&g_S1[o], s1);
    atomicAdd(&g_S2[o], s2);
}

__global__ void k_pool(const float* __restrict__ gam, const float* __restrict__ bet,
                       float* __restrict__ out){
    int b = blockIdx.x, o = threadIdx.x;
    const float ci = 1.f/(float)ROWS;
    float mean = g_S1[o]*ci;
    float var  = g_S2[o]*ci - mean*mean;
    float sc = gam[o]*rsqrtf(var + EPSBN);
    float sh = bet[o] - mean*sc;
    float mx = -3.4e38f, sum = 0.f;
    const float* hb = g_h5 + (size_t)b*NPTS*512;
#pragma unroll 4
    for (int n=0;n<NPTS;n++){
        float h = hb[(size_t)n*512 + o]*sc + sh;
        h = h >= 0.f ? h : SLOPE*h;
        mx = fmaxf(mx,h); sum += h;
    }
    out[b*1024 + o]       = mx;
    out[b*1024 + 512 + o] = sum*(1.f/(float)NPTS);
}

extern "C" void kernel_launch(void* const* d_in, const int* in_sizes, int n_in,
                              void* d_out, int out_size){
    const float* x   = (const float*)d_in[0];
    const float* W1  = (const float*)d_in[2];
    const float* G1  = (const float*)d_in[3];
    const float* Bb1 = (const float*)d_in[4];
    const float* W2  = (const float*)d_in[5];
    const float* G2  = (const float*)d_in[6];
    const float* Bb2 = (const float*)d_in[7];
    const float* W3  = (const float*)d_in[8];
    const float* G3  = (const float*)d_in[9];
    const float* Bb3 = (const float*)d_in[10];
    const float* W4  = (const float*)d_in[11];
    const float* G4  = (const float*)d_in[12];
    const float* Bb4 = (const float*)d_in[13];
    const float* W5  = (const float*)d_in[14];
    const float* G5  = (const float*)d_in[15];
    const float* Bb5 = (const float*)d_in[16];
    float* out = (float*)d_out;

    float *px0,*px1,*px2,*px3,*px4,*pA,*pB;
    cudaGetSymbolAddress((void**)&px0, g_x0);
    cudaGetSymbolAddress((void**)&px1, g_x1);
    cudaGetSymbolAddress((void**)&px2, g_x2);
    cudaGetSymbolAddress((void**)&px3, g_x3);
    cudaGetSymbolAddress((void**)&px4, g_x4);
    cudaGetSymbolAddress((void**)&pA,  g_A);
    cudaGetSymbolAddress((void**)&pB,  g_Bm);

    dim3 gd(136, 1, BATCH);   // upper-triangle tiles x batch

    k_trans0<<<ROWS/256, 256>>>(x);

    // block 1: C=3 -> O=64
    k_dist_sym<3><<<gd, 256>>>(px0);
    k_topk<<<ROWS/4, 128>>>();
    k_ab<3,64><<<dim3(1, ROWS/64), 256>>>(px0, W1, pA, pB);
    k_gather<64><<<ROWS/8, 64>>>(pA, pB, px1);
    k_apply<64><<<(ROWS*64)/256, 256>>>(px1, G1, Bb1);

    // block 2: C=64 -> O=64
    k_norm<64><<<(ROWS*32)/256, 256>>>(px1);
    k_dist_sym<64><<<gd, 256>>>(px1);
    k_topk<<<ROWS/4, 128>>>();
    k_ab<64,64><<<dim3(1, ROWS/64), 256>>>(px1, W2, pA, pB);
    k_gather<64><<<ROWS/8, 64>>>(pA, pB, px2);
    k_apply<64><<<(ROWS*64)/256, 256>>>(px2, G2, Bb2);

    // block 3: C=64 -> O=128
    k_norm<64><<<(ROWS*32)/256, 256>>>(px2);
    k_dist_sym<64><<<gd, 256>>>(px2);
    k_topk<<<ROWS/4, 128>>>();
    k_ab<64,128><<<dim3(2, ROWS/64), 256>>>(px2, W3, pA, pB);
    k_gather<128><<<ROWS/8, 128>>>(pA, pB, px3);
    k_apply<128><<<(ROWS*128)/256, 256>>>(px3, G3, Bb3);

    // block 4: C=128 -> O=256
    k_norm<128><<<(ROWS*32)/256, 256>>>(px3);
    k_dist_sym<128><<<gd, 256>>>(px3);
    k_topk<<<ROWS/4, 128>>>();
    k_ab<128,256><<<dim3(4, ROWS/64), 256>>>(px3, W4, pA, pB);
    k_gather<256><<<ROWS/8, 256>>>(pA, pB, px4);
    k_apply<256><<<(ROWS*256)/256, 256>>>(px4, G4, Bb4);

    // final
    k_gemm5<<<dim3(4, ROWS/128), 256>>>(W5);
    k_stats5<<<64, 512>>>();
    k_pool<<<BATCH, 512>>>(G5, Bb5, out);
}